// round 15
// baseline (speedup 1.0000x reference)
#include <cuda_runtime.h>
#include <cuda_fp16.h>
#include <math.h>
#include <stdint.h>

// ---------------- problem constants ----------------
#define B_   2
#define S_   4096
#define DM_  768
#define DI_  1152
#define H_   12
#define DH_  64
#define ROWS (B_ * S_)          // 8192
#define DQKV (3 * DM_)          // 2304
#define WIN  64                 // WINDOW/2

// ---------------- scratch ----------------
__device__ __half g_h[ROWS * DM_];
__device__ float  g_qkv[ROWS * DQKV];
__device__ __half g_attn[ROWS * DM_];
__device__ float  g_x1[ROWS * DM_];
__device__ __half g_act[ROWS * DI_];
__device__ float2 g_rope[S_ * 32];
__device__ __half g_wqkv[DQKV * DM_];
__device__ __half g_wo  [DM_ * DM_];
__device__ __half g_wi01[2 * DI_ * DM_];
__device__ __half g_wmo [DM_ * DI_];

__device__ __forceinline__ float warpSum(float v) {
    #pragma unroll
    for (int o = 16; o; o >>= 1) v += __shfl_xor_sync(0xffffffffu, v, o);
    return v;
}

// ---------------- merged prep: 5 weights + rope table ----------------
__global__ void wprep_kernel(const float* __restrict__ w_qkv, const float* __restrict__ w_o,
                             const float* __restrict__ w_i0,  const float* __restrict__ w_i1,
                             const float* __restrict__ w_mo,
                             __half* __restrict__ o_qkv, __half* __restrict__ o_o,
                             __half* __restrict__ o_i01, __half* __restrict__ o_mo,
                             float2* __restrict__ ropeTab) {
    int tx = threadIdx.x, ty = threadIdx.y;
    if (blockIdx.z == 5) {
        // rope table: need S_*32 = 131072 entries; 512 blocks of 256 threads
        int bid = blockIdx.y * gridDim.x + blockIdx.x;
        int idx = bid * 256 + ty * 32 + tx;
        if (idx < S_ * 32) {
            int s = idx >> 5, d = idx & 31;
            float w = (float)(2 * d) / (float)DH_;
            float inv_freq = 1.0f / powf(10000.0f, w);
            float ang = (float)s * inv_freq;
            ropeTab[idx] = make_float2(cosf(ang), sinf(ang));
        }
        return;
    }
    const float* in; __half* out; int K, N, mapMode;
    switch (blockIdx.z) {
        case 0: in = w_qkv; out = o_qkv; K = DM_; N = DQKV; mapMode = 0; break;
        case 1: in = w_o;   out = o_o;   K = DM_; N = DM_;  mapMode = 0; break;
        case 2: in = w_i0;  out = o_i01; K = DM_; N = DI_;  mapMode = 1; break;
        case 3: in = w_i1;  out = o_i01; K = DM_; N = DI_;  mapMode = 2; break;
        default:in = w_mo;  out = o_mo;  K = DI_; N = DM_;  mapMode = 0; break;
    }
    int k0 = blockIdx.x * 32, n0 = blockIdx.y * 32;
    if (k0 >= K || n0 >= N) return;
    __shared__ float t[32][33];
    #pragma unroll
    for (int i = ty; i < 32; i += 8)
        t[i][tx] = in[(size_t)(k0 + i) * N + n0 + tx];
    __syncthreads();
    #pragma unroll
    for (int i = ty; i < 32; i += 8) {
        int n = n0 + i;
        int row;
        if (mapMode == 0)      row = n;
        else if (mapMode == 1) row = ((n >> 3) << 4) + (n & 7);
        else                   row = ((n >> 3) << 4) + 8 + (n & 7);
        out[(size_t)row * K + k0 + tx] = __float2half_rn(t[tx][i]);
    }
}

// ---------------- RMSNorm (vectorized, fp16 output) ----------------
__global__ void rmsnorm_kernel(const float* __restrict__ x,
                               const float* __restrict__ gamma,
                               __half* __restrict__ o) {
    int row = blockIdx.x;
    const float4* xr = (const float4*)(x + (size_t)row * DM_);
    const int tid = threadIdx.x;
    float4 v4 = make_float4(0.f, 0.f, 0.f, 0.f);
    if (tid < 192) v4 = xr[tid];
    float s = v4.x * v4.x + v4.y * v4.y + v4.z * v4.z + v4.w * v4.w;
    __shared__ float red[8];
    float w = warpSum(s);
    if ((tid & 31) == 0) red[tid >> 5] = w;
    __syncthreads();
    float tot = 0.f;
    #pragma unroll
    for (int i = 0; i < 8; i++) tot += red[i];
    float inv = rsqrtf(tot / (float)DM_ + 1e-5f);
    if (tid < 192) {
        float4 g4 = ((const float4*)gamma)[tid];
        __half2 h0 = __floats2half2_rn(v4.x * inv * g4.x, v4.y * inv * g4.y);
        __half2 h1 = __floats2half2_rn(v4.z * inv * g4.z, v4.w * inv * g4.w);
        __half* orow = o + (size_t)row * DM_;
        *(__half2*)&orow[tid * 4]     = h0;
        *(__half2*)&orow[tid * 4 + 2] = h1;
    }
}

// =================== fp16 tensor-core GEMM, BN templated ====
#define BM 128
#define BK 64
#define HSTRIDE 72
#define NSTAGE 3

__device__ __forceinline__ void mma_f16(float c[4], const uint32_t a[4], const uint32_t b[2]) {
    asm volatile(
        "mma.sync.aligned.m16n8k16.row.col.f32.f16.f16.f32 "
        "{%0,%1,%2,%3}, {%4,%5,%6,%7}, {%8,%9}, {%0,%1,%2,%3};"
        : "+f"(c[0]), "+f"(c[1]), "+f"(c[2]), "+f"(c[3])
        : "r"(a[0]), "r"(a[1]), "r"(a[2]), "r"(a[3]), "r"(b[0]), "r"(b[1]));
}

__device__ __forceinline__ void ldsm_x4(uint32_t r[4], uint32_t saddr) {
    asm volatile("ldmatrix.sync.aligned.m8n8.x4.shared.b16 {%0,%1,%2,%3}, [%4];"
        : "=r"(r[0]), "=r"(r[1]), "=r"(r[2]), "=r"(r[3]) : "r"(saddr));
}

__device__ __forceinline__ void cp16(const __half* dst_smem, const __half* src) {
    uint32_t d = (uint32_t)__cvta_generic_to_shared(dst_smem);
    asm volatile("cp.async.cg.shared.global [%0], [%1], 16;" :: "r"(d), "l"(src));
}

__device__ __forceinline__ float gelu_t(float x) {
    float t = tanhf(0.7978845608028654f * (x + 0.044715f * x * x * x));
    return 0.5f * x * (1.0f + t);
}

// mode 0: C=acc(f32) ; 1: C=Res+acc(f32) ; 3: fused gate/up (BNT==128 only)
template <int BNT>
__global__ __launch_bounds__(256, 2)
void mma_gemm_kernel(const __half* __restrict__ A, const __half* __restrict__ Bt,
                     const float* __restrict__ Res, void* __restrict__ Cv,
                     int M, int N, int K, int mode) {
    constexpr int NT  = BNT / 16;        // n-tiles of 8 per warp
    constexpr int NTP = NT / 2;          // ldsm x4 B loads per ks
    constexpr int STAGE_HALVES = (BM + BNT) * HSTRIDE;
    constexpr int STAGE_BYTES  = STAGE_HALVES * 2;

    extern __shared__ __half smh[];

    const int tid  = threadIdx.x;
    const int lane = tid & 31;
    const int warp = tid >> 5;
    const int gid  = lane >> 2;
    const int tg   = lane & 3;
    const int wm   = warp >> 1;
    const int wn   = warp & 1;

    const int bm = blockIdx.y * BM;
    const int bn = blockIdx.x * BNT;

    const uint32_t smBase = (uint32_t)__cvta_generic_to_shared(smh);
    const int rowA0 = wm * 32 + (lane & 15);
    const int koffA = (lane >> 4) << 3;
    const int rowB0 = wn * (BNT / 2) + (lane & 7) + ((lane >> 4) << 3);
    const int koffB = ((lane >> 3) & 1) << 3;

    float acc[2][NT][4];
    #pragma unroll
    for (int i = 0; i < 2; i++)
        #pragma unroll
        for (int j = 0; j < NT; j++)
            #pragma unroll
            for (int l = 0; l < 4; l++) acc[i][j][l] = 0.f;

    const int ntiles = K / BK;

    // A: 128x64 halves = 1024 chunks (4/thr) ; B: BNT x 64 halves (BNT/32 /thr)
    #define ISSUE_TILE(t, buf) do {                                            \
        __half* As_ = smh + (buf) * STAGE_HALVES;                               \
        __half* Bs_ = As_ + BM * HSTRIDE;                                       \
        int k0_ = (t) * BK;                                                     \
        _Pragma("unroll")                                                       \
        for (int u = 0; u < 4; u++) {                                           \
            int i = tid + u * 256;                                              \
            int r = i >> 3, c = i & 7;                                          \
            cp16(&As_[r * HSTRIDE + c * 8],                                     \
                 &A[(size_t)(bm + r) * K + k0_ + c * 8]);                       \
        }                                                                       \
        _Pragma("unroll")                                                       \
        for (int u = 0; u < BNT / 32; u++) {                                    \
            int i = tid + u * 256;                                              \
            int r = i >> 3, c = i & 7;                                          \
            cp16(&Bs_[r * HSTRIDE + c * 8],                                     \
                 &Bt[(size_t)(bn + r) * K + k0_ + c * 8]);                      \
        }                                                                       \
        asm volatile("cp.async.commit_group;");                                 \
    } while (0)

    ISSUE_TILE(0, 0);
    if (ntiles > 1) ISSUE_TILE(1, 1);

    int buf = 0;
    for (int t = 0; t < ntiles; t++) {
        if (t + 1 < ntiles) asm volatile("cp.async.wait_group 1;");
        else                asm volatile("cp.async.wait_group 0;");
        __syncthreads();

        if (t + 2 < ntiles) {
            int nb = buf + 2; if (nb >= NSTAGE) nb -= NSTAGE;
            ISSUE_TILE(t + 2, nb);
        }

        const uint32_t aBase = smBase + buf * STAGE_BYTES;
        const uint32_t bBase = aBase + BM * HSTRIDE * 2;

        #pragma unroll
        for (int ks = 0; ks < 4; ks++) {
            uint32_t af[2][4], bf[NT][2];
            #pragma unroll
            for (int mt = 0; mt < 2; mt++) {
                ldsm_x4(af[mt],
                        aBase + ((rowA0 + mt * 16) * HSTRIDE + ks * 16 + koffA) * 2);
            }
            #pragma unroll
            for (int ntp = 0; ntp < NTP; ntp++) {
                uint32_t r[4];
                ldsm_x4(r, bBase + ((rowB0 + ntp * 16) * HSTRIDE + ks * 16 + koffB) * 2);
                bf[2 * ntp][0]     = r[0];
                bf[2 * ntp][1]     = r[1];
                bf[2 * ntp + 1][0] = r[2];
                bf[2 * ntp + 1][1] = r[3];
            }
            #pragma unroll
            for (int mt = 0; mt < 2; mt++)
                #pragma unroll
                for (int nt = 0; nt < NT; nt++)
                    mma_f16(acc[mt][nt], af[mt], bf[nt]);
        }

        buf++; if (buf >= NSTAGE) buf = 0;
    }

    if (BNT == 128 && mode == 3) {
        __half* Ch = (__half*)Cv;
        #pragma unroll
        for (int mt = 0; mt < 2; mt++) {
            #pragma unroll
            for (int ntp = 0; ntp < NTP; ntp++) {
                int m0 = bm + wm * 32 + mt * 16 + gid;
                int oc = (bn >> 1) + wn * 32 + ntp * 8 + tg * 2;
                float* g = acc[mt][2 * ntp];
                float* u = acc[mt][2 * ntp + 1];
                *(__half2*)&Ch[(size_t)m0 * DI_ + oc] =
                    __floats2half2_rn(gelu_t(g[0]) * u[0], gelu_t(g[1]) * u[1]);
                *(__half2*)&Ch[(size_t)(m0 + 8) * DI_ + oc] =
                    __floats2half2_rn(gelu_t(g[2]) * u[2], gelu_t(g[3]) * u[3]);
            }
        }
        return;
    }

    #pragma unroll
    for (int mt = 0; mt < 2; mt++) {
        #pragma unroll
        for (int nt = 0; nt < NT; nt++) {
            int m0 = bm + wm * 32 + mt * 16 + gid;
            int n0 = bn + wn * (BNT / 2) + nt * 8 + tg * 2;
            float2 v0 = make_float2(acc[mt][nt][0], acc[mt][nt][1]);
            float2 v1 = make_float2(acc[mt][nt][2], acc[mt][nt][3]);
            if (mode == 1) {
                float2 r0 = *(const float2*)&Res[(size_t)m0 * N + n0];
                float2 r1 = *(const float2*)&Res[(size_t)(m0 + 8) * N + n0];
                v0.x += r0.x; v0.y += r0.y;
                v1.x += r1.x; v1.y += r1.y;
            }
            float* C = (float*)Cv;
            *(float2*)&C[(size_t)m0 * N + n0] = v0;
            *(float2*)&C[(size_t)(m0 + 8) * N + n0] = v1;
        }
    }
}

#define GEMM_SMEM_128 (NSTAGE * (BM + 128) * HSTRIDE * 2)
#define GEMM_SMEM_64  (NSTAGE * (BM + 64)  * HSTRIDE * 2)

// =================== tensor-core sliding-window attention (R11-14) ====
#define QT 64
#define KT 192
#define KTP 72
#define VTP 200
#define ATTN_SMEM_BYTES ((QT * KTP + KT * KTP + DH_ * VTP) * 2 + KT * 4)

__device__ __forceinline__ void rope_h(const float2* __restrict__ tab, int s, int c,
                                       float4 lo, float4 hi, __half2 olo[2], __half2 ohi[2]) {
    float rlo[4], rhi[4];
    #pragma unroll
    for (int l = 0; l < 4; l++) {
        float2 cs = tab[s * 32 + c * 4 + l];
        float x1 = (&lo.x)[l];
        float x2 = (&hi.x)[l];
        rlo[l] = x1 * cs.x - x2 * cs.y;
        rhi[l] = x2 * cs.x + x1 * cs.y;
    }
    olo[0] = __floats2half2_rn(rlo[0], rlo[1]);
    olo[1] = __floats2half2_rn(rlo[2], rlo[3]);
    ohi[0] = __floats2half2_rn(rhi[0], rhi[1]);
    ohi[1] = __floats2half2_rn(rhi[2], rhi[3]);
}

__global__ __launch_bounds__(128)
void attn_mma_kernel(const float* __restrict__ qkv, const int* __restrict__ pmask,
                     const float2* __restrict__ ropeT, __half* __restrict__ out) {
    extern __shared__ __half smh[];
    __half* Qh = smh;
    __half* Kh = Qh + QT * KTP;
    __half* Vt = Kh + KT * KTP;
    float*  pm = (float*)(Vt + DH_ * VTP);

    const int qt0 = blockIdx.x * QT;
    const int h   = blockIdx.y;
    const int b   = blockIdx.z;
    const int tid = threadIdx.x;
    const int lane = tid & 31;
    const int warp = tid >> 5;
    const int gid  = lane >> 2;
    const int tg   = lane & 3;

    for (int i = tid; i < KT; i += 128) {
        int j = qt0 - WIN + i;
        pm[i] = (j < 0 || j >= S_) ? -1e30f : (pmask[b * S_ + j] ? 0.f : -10000.0f);
    }
    #pragma unroll
    for (int it = 0; it < 4; it++) {
        int i = tid + it * 128;
        int r = i >> 3, c = i & 7;
        int s = qt0 + r;
        size_t base = (size_t)(b * S_ + s) * DQKV + h * DH_;
        float4 lo = *(const float4*)&qkv[base + c * 4];
        float4 hi = *(const float4*)&qkv[base + 32 + c * 4];
        __half2 olo[2], ohi[2];
        rope_h(ropeT, s, c, lo, hi, olo, ohi);
        *(__half2*)&Qh[r * KTP + c * 4]      = olo[0];
        *(__half2*)&Qh[r * KTP + c * 4 + 2]  = olo[1];
        *(__half2*)&Qh[r * KTP + 32 + c * 4]     = ohi[0];
        *(__half2*)&Qh[r * KTP + 32 + c * 4 + 2] = ohi[1];
    }
    #pragma unroll
    for (int it = 0; it < 12; it++) {
        int i = tid + it * 128;
        int r = i >> 3, c = i & 7;
        int j = qt0 - WIN + r;
        __half2 olo[2], ohi[2];
        if (j >= 0 && j < S_) {
            size_t base = (size_t)(b * S_ + j) * DQKV + DM_ + h * DH_;
            float4 lo = *(const float4*)&qkv[base + c * 4];
            float4 hi = *(const float4*)&qkv[base + 32 + c * 4];
            rope_h(ropeT, j, c, lo, hi, olo, ohi);
        } else {
            olo[0] = olo[1] = ohi[0] = ohi[1] = __floats2half2_rn(0.f, 0.f);
        }
        *(__half2*)&Kh[r * KTP + c * 4]      = olo[0];
        *(__half2*)&Kh[r * KTP + c * 4 + 2]  = olo[1];
        *(__half2*)&Kh[r * KTP + 32 + c * 4]     = ohi[0];
        *(__half2*)&Kh[r * KTP + 32 + c * 4 + 2] = ohi[1];
    }
    #pragma unroll
    for (int it = 0; it < 24; it++) {
        int i = tid + it * 128;
        int r = i >> 4, c = i & 15;
        int j = qt0 - WIN + r;
        float4 v = make_float4(0.f, 0.f, 0.f, 0.f);
        if (j >= 0 && j < S_)
            v = *(const float4*)&qkv[(size_t)(b * S_ + j) * DQKV + 2 * DM_ + h * DH_ + c * 4];
        Vt[(c * 4 + 0) * VTP + r] = __float2half_rn(v.x);
        Vt[(c * 4 + 1) * VTP + r] = __float2half_rn(v.y);
        Vt[(c * 4 + 2) * VTP + r] = __float2half_rn(v.z);
        Vt[(c * 4 + 3) * VTP + r] = __float2half_rn(v.w);
    }
    __syncthreads();

    const int rq = warp * 16;
    float acc[24][4];
    #pragma unroll
    for (int nt = 0; nt < 24; nt++)
        #pragma unroll
        for (int e = 0; e < 4; e++) acc[nt][e] = 0.f;

    #pragma unroll
    for (int ks = 0; ks < 4; ks++) {
        const int kb = ks * 16 + 2 * tg;
        uint32_t a[4];
        a[0] = *(const uint32_t*)&Qh[(rq + gid) * KTP + kb];
        a[1] = *(const uint32_t*)&Qh[(rq + gid + 8) * KTP + kb];
        a[2] = *(const uint32_t*)&Qh[(rq + gid) * KTP + kb + 8];
        a[3] = *(const uint32_t*)&Qh[(rq + gid + 8) * KTP + kb + 8];
        #pragma unroll
        for (int nt = 0; nt < 24; nt++) {
            int n = nt * 8 + gid;
            uint32_t bfr[2];
            bfr[0] = *(const uint32_t*)&Kh[n * KTP + kb];
            bfr[1] = *(const uint32_t*)&Kh[n * KTP + kb + 8];
            mma_f16(acc[nt], a, bfr);
        }
    }

    const int ql0 = rq + gid;
    float m0 = -1e30f, m1 = -1e30f;
    #pragma unroll
    for (int nt = 0; nt < 24; nt++) {
        #pragma unroll
        for (int e = 0; e < 4; e++) {
            int col = nt * 8 + 2 * tg + (e & 1);
            int ql  = ql0 + ((e >> 1) << 3);
            float s = acc[nt][e] * 0.125f + pm[col];
            int d = col - ql - WIN;
            if (d > WIN || d < -WIN) s -= 10000.0f;
            acc[nt][e] = s;
            if (e < 2) m0 = fmaxf(m0, s); else m1 = fmaxf(m1, s);
        }
    }
    m0 = fmaxf(m0, __shfl_xor_sync(0xffffffffu, m0, 1));
    m0 = fmaxf(m0, __shfl_xor_sync(0xffffffffu, m0, 2));
    m1 = fmaxf(m1, __shfl_xor_sync(0xffffffffu, m1, 1));
    m1 = fmaxf(m1, __shfl_xor_sync(0xffffffffu, m1, 2));

    float s0 = 0.f, s1 = 0.f;
    #pragma unroll
    for (int nt = 0; nt < 24; nt++) {
        float e0 = expf(acc[nt][0] - m0);
        float e1 = expf(acc[nt][1] - m0);
        float e2 = expf(acc[nt][2] - m1);
        float e3 = expf(acc[nt][3] - m1);
        acc[nt][0] = e0; acc[nt][1] = e1; acc[nt][2] = e2; acc[nt][3] = e3;
        s0 += e0 + e1; s1 += e2 + e3;
    }
    s0 += __shfl_xor_sync(0xffffffffu, s0, 1);
    s0 += __shfl_xor_sync(0xffffffffu, s0, 2);
    s1 += __shfl_xor_sync(0xffffffffu, s1, 1);
    s1 += __shfl_xor_sync(0xffffffffu, s1, 2);
    const float inv0 = 1.0f / s0;
    const float inv1 = 1.0f / s1;

    float accV[8][4];
    #pragma unroll
    for (int nt = 0; nt < 8; nt++)
        #pragma unroll
        for (int e = 0; e < 4; e++) accV[nt][e] = 0.f;

    #pragma unroll
    for (int ks = 0; ks < 12; ks++) {
        uint32_t a[4];
        __half2 h0 = __floats2half2_rn(acc[2 * ks][0] * inv0,     acc[2 * ks][1] * inv0);
        __half2 h1 = __floats2half2_rn(acc[2 * ks][2] * inv1,     acc[2 * ks][3] * inv1);
        __half2 h2 = __floats2half2_rn(acc[2 * ks + 1][0] * inv0, acc[2 * ks + 1][1] * inv0);
        __half2 h3 = __floats2half2_rn(acc[2 * ks + 1][2] * inv1, acc[2 * ks + 1][3] * inv1);
        a[0] = *(uint32_t*)&h0;
        a[1] = *(uint32_t*)&h1;
        a[2] = *(uint32_t*)&h2;
        a[3] = *(uint32_t*)&h3;
        const int kb = ks * 16 + 2 * tg;
        #pragma unroll
        for (int nt = 0; nt < 8; nt++) {
            int n = nt * 8 + gid;
            uint32_t bfr[2];
            bfr[0] = *(const uint32_t*)&Vt[n * VTP + kb];
            bfr[1] = *(const uint32_t*)&Vt[n * VTP + kb + 8];
            mma_f16(accV[nt], a, bfr);
        }
    }

    #pragma unroll
    for (int nt = 0; nt < 8; nt++) {
        int col = h * DH_ + nt * 8 + 2 * tg;
        size_t r0 = (size_t)(b * S_ + qt0 + ql0) * DM_ + col;
        size_t r1 = (size_t)(b * S_ + qt0 + ql0 + 8) * DM_ + col;
        *(__half2*)&out[r0] = __floats2half2_rn(accV[nt][0], accV[nt][1]);
        *(__half2*)&out[r1] = __floats2half2_rn(accV[nt][2], accV[nt][3]);
    }
}

// ---------------- launch ----------------
extern "C" void kernel_launch(void* const* d_in, const int* in_sizes, int n_in,
                              void* d_out, int out_size) {
    const float* x          = (const float*)d_in[0];
    const int*   pmask      = (const int*)  d_in[1];
    const float* w_qkv      = (const float*)d_in[2];
    const float* w_o        = (const float*)d_in[3];
    const float* gamma_attn = (const float*)d_in[4];
    const float* gamma_mlp  = (const float*)d_in[5];
    const float* w_i0       = (const float*)d_in[6];
    const float* w_i1       = (const float*)d_in[7];
    const float* w_mo       = (const float*)d_in[8];
    float* out = (float*)d_out;

    __half *h, *attn, *act, *wqkv, *wo, *wi01, *wmo;
    float *qkv, *x1;
    float2* ropeT;
    cudaGetSymbolAddress((void**)&h,    g_h);
    cudaGetSymbolAddress((void**)&qkv,  g_qkv);
    cudaGetSymbolAddress((void**)&attn, g_attn);
    cudaGetSymbolAddress((void**)&x1,   g_x1);
    cudaGetSymbolAddress((void**)&act,  g_act);
    cudaGetSymbolAddress((void**)&ropeT, g_rope);
    cudaGetSymbolAddress((void**)&wqkv, g_wqkv);
    cudaGetSymbolAddress((void**)&wo,   g_wo);
    cudaGetSymbolAddress((void**)&wi01, g_wi01);
    cudaGetSymbolAddress((void**)&wmo,  g_wmo);

    cudaFuncSetAttribute(mma_gemm_kernel<128>,
                         cudaFuncAttributeMaxDynamicSharedMemorySize, GEMM_SMEM_128);
    cudaFuncSetAttribute(mma_gemm_kernel<64>,
                         cudaFuncAttributeMaxDynamicSharedMemorySize, GEMM_SMEM_64);
    cudaFuncSetAttribute(attn_mma_kernel,
                         cudaFuncAttributeMaxDynamicSharedMemorySize, ATTN_SMEM_BYTES);

    // merged prep: weights (z=0..4) + rope table (z=5)
    wprep_kernel<<<dim3(DI_ / 32, DQKV / 32, 6), dim3(32, 8)>>>(
        w_qkv, w_o, w_i0, w_i1, w_mo, wqkv, wo, wi01, wmo, ropeT);

    rmsnorm_kernel<<<ROWS, 256>>>(x, gamma_attn, h);
    mma_gemm_kernel<128><<<dim3(DQKV / 128, ROWS / BM), 256, GEMM_SMEM_128>>>(
        h, wqkv, nullptr, qkv, ROWS, DQKV, DM_, 0);
    attn_mma_kernel<<<dim3(S_ / QT, H_, B_), 128, ATTN_SMEM_BYTES>>>(qkv, pmask, ropeT, attn);
    mma_gemm_kernel<64><<<dim3(DM_ / 64, ROWS / BM), 256, GEMM_SMEM_64>>>(
        attn, wo, x, x1, ROWS, DM_, DM_, 1);
    rmsnorm_kernel<<<ROWS, 256>>>(x1, gamma_mlp, h);
    mma_gemm_kernel<128><<<dim3(2 * DI_ / 128, ROWS / BM), 256, GEMM_SMEM_128>>>(
        h, wi01, nullptr, act, ROWS, 2 * DI_, DM_, 3);
    mma_gemm_kernel<64><<<dim3(DM_ / 64, ROWS / BM), 256, GEMM_SMEM_64>>>(
        act, wmo, x1, out, ROWS, DM_, DI_, 1);
}

// round 16
// speedup vs baseline: 1.0332x; 1.0332x over previous
#include <cuda_runtime.h>
#include <cuda_fp16.h>
#include <math.h>
#include <stdint.h>

// ---------------- problem constants ----------------
#define B_   2
#define S_   4096
#define DM_  768
#define DI_  1152
#define H_   12
#define DH_  64
#define ROWS (B_ * S_)          // 8192
#define DQKV (3 * DM_)          // 2304
#define WIN  64                 // WINDOW/2

// ---------------- scratch ----------------
__device__ __half g_h[ROWS * DM_];
__device__ float  g_qkv[ROWS * DQKV];
__device__ __half g_attn[ROWS * DM_];
__device__ float  g_x1[ROWS * DM_];
__device__ __half g_act[ROWS * DI_];
__device__ float2 g_rope[S_ * 32];
__device__ __half g_wqkv[DQKV * DM_];
__device__ __half g_wo  [DM_ * DM_];
__device__ __half g_wi01[2 * DI_ * DM_];
__device__ __half g_wmo [DM_ * DI_];

__device__ __forceinline__ float warpSum(float v) {
    #pragma unroll
    for (int o = 16; o; o >>= 1) v += __shfl_xor_sync(0xffffffffu, v, o);
    return v;
}

// ---------------- merged prep: 5 weights + rope table ----------------
__global__ void wprep_kernel(const float* __restrict__ w_qkv, const float* __restrict__ w_o,
                             const float* __restrict__ w_i0,  const float* __restrict__ w_i1,
                             const float* __restrict__ w_mo,
                             __half* __restrict__ o_qkv, __half* __restrict__ o_o,
                             __half* __restrict__ o_i01, __half* __restrict__ o_mo,
                             float2* __restrict__ ropeTab) {
    int tx = threadIdx.x, ty = threadIdx.y;
    if (blockIdx.z == 5) {
        int bid = blockIdx.y * gridDim.x + blockIdx.x;
        int idx = bid * 256 + ty * 32 + tx;
        if (idx < S_ * 32) {
            int s = idx >> 5, d = idx & 31;
            float w = (float)(2 * d) / (float)DH_;
            float inv_freq = 1.0f / powf(10000.0f, w);
            float ang = (float)s * inv_freq;
            ropeTab[idx] = make_float2(cosf(ang), sinf(ang));
        }
        return;
    }
    const float* in; __half* out; int K, N, mapMode;
    switch (blockIdx.z) {
        case 0: in = w_qkv; out = o_qkv; K = DM_; N = DQKV; mapMode = 0; break;
        case 1: in = w_o;   out = o_o;   K = DM_; N = DM_;  mapMode = 0; break;
        case 2: in = w_i0;  out = o_i01; K = DM_; N = DI_;  mapMode = 1; break;
        case 3: in = w_i1;  out = o_i01; K = DM_; N = DI_;  mapMode = 2; break;
        default:in = w_mo;  out = o_mo;  K = DI_; N = DM_;  mapMode = 0; break;
    }
    int k0 = blockIdx.x * 32, n0 = blockIdx.y * 32;
    if (k0 >= K || n0 >= N) return;
    __shared__ float t[32][33];
    #pragma unroll
    for (int i = ty; i < 32; i += 8)
        t[i][tx] = in[(size_t)(k0 + i) * N + n0 + tx];
    __syncthreads();
    #pragma unroll
    for (int i = ty; i < 32; i += 8) {
        int n = n0 + i;
        int row;
        if (mapMode == 0)      row = n;
        else if (mapMode == 1) row = ((n >> 3) << 4) + (n & 7);
        else                   row = ((n >> 3) << 4) + 8 + (n & 7);
        out[(size_t)row * K + k0 + tx] = __float2half_rn(t[tx][i]);
    }
}

// ---------------- RMSNorm ----------------
__global__ void rmsnorm_kernel(const float* __restrict__ x,
                               const float* __restrict__ gamma,
                               __half* __restrict__ o) {
    int row = blockIdx.x;
    const float4* xr = (const float4*)(x + (size_t)row * DM_);
    const int tid = threadIdx.x;
    float4 v4 = make_float4(0.f, 0.f, 0.f, 0.f);
    if (tid < 192) v4 = xr[tid];
    float s = v4.x * v4.x + v4.y * v4.y + v4.z * v4.z + v4.w * v4.w;
    __shared__ float red[8];
    float w = warpSum(s);
    if ((tid & 31) == 0) red[tid >> 5] = w;
    __syncthreads();
    float tot = 0.f;
    #pragma unroll
    for (int i = 0; i < 8; i++) tot += red[i];
    float inv = rsqrtf(tot / (float)DM_ + 1e-5f);
    if (tid < 192) {
        float4 g4 = ((const float4*)gamma)[tid];
        __half2 h0 = __floats2half2_rn(v4.x * inv * g4.x, v4.y * inv * g4.y);
        __half2 h1 = __floats2half2_rn(v4.z * inv * g4.z, v4.w * inv * g4.w);
        __half* orow = o + (size_t)row * DM_;
        *(__half2*)&orow[tid * 4]     = h0;
        *(__half2*)&orow[tid * 4 + 2] = h1;
    }
}

// =================== fp16 tensor-core GEMM (R14 config: 128x128x64) ====
#define BM 128
#define BN 128
#define BK 64
#define HSTRIDE 72
#define STAGE_HALVES ((BM + BN) * HSTRIDE)
#define STAGE_BYTES (STAGE_HALVES * 2)
#define NSTAGE 3
#define GEMM_SMEM_BYTES (NSTAGE * STAGE_BYTES)

__device__ __forceinline__ void mma_f16(float c[4], const uint32_t a[4], const uint32_t b[2]) {
    asm volatile(
        "mma.sync.aligned.m16n8k16.row.col.f32.f16.f16.f32 "
        "{%0,%1,%2,%3}, {%4,%5,%6,%7}, {%8,%9}, {%0,%1,%2,%3};"
        : "+f"(c[0]), "+f"(c[1]), "+f"(c[2]), "+f"(c[3])
        : "r"(a[0]), "r"(a[1]), "r"(a[2]), "r"(a[3]), "r"(b[0]), "r"(b[1]));
}

__device__ __forceinline__ void ldsm_x4(uint32_t r[4], uint32_t saddr) {
    asm volatile("ldmatrix.sync.aligned.m8n8.x4.shared.b16 {%0,%1,%2,%3}, [%4];"
        : "=r"(r[0]), "=r"(r[1]), "=r"(r[2]), "=r"(r[3]) : "r"(saddr));
}

__device__ __forceinline__ void cp16(const __half* dst_smem, const __half* src) {
    uint32_t d = (uint32_t)__cvta_generic_to_shared(dst_smem);
    asm volatile("cp.async.cg.shared.global [%0], [%1], 16;" :: "r"(d), "l"(src));
}

__device__ __forceinline__ float gelu_t(float x) {
    float t = tanhf(0.7978845608028654f * (x + 0.044715f * x * x * x));
    return 0.5f * x * (1.0f + t);
}

__global__ __launch_bounds__(256, 2)
void mma_gemm_kernel(const __half* __restrict__ A, const __half* __restrict__ Bt,
                     const float* __restrict__ Res, void* __restrict__ Cv,
                     int M, int N, int K, int mode) {
    extern __shared__ __half smh[];

    const int tid  = threadIdx.x;
    const int lane = tid & 31;
    const int warp = tid >> 5;
    const int gid  = lane >> 2;
    const int tg   = lane & 3;
    const int wm   = warp >> 1;
    const int wn   = warp & 1;

    const int bm = blockIdx.y * BM;
    const int bn = blockIdx.x * BN;

    const uint32_t smBase = (uint32_t)__cvta_generic_to_shared(smh);
    const int rowA0 = wm * 32 + (lane & 15);
    const int koffA = (lane >> 4) << 3;
    const int rowB0 = wn * 64 + (lane & 7) + ((lane >> 4) << 3);
    const int koffB = ((lane >> 3) & 1) << 3;

    float acc[2][8][4];
    #pragma unroll
    for (int i = 0; i < 2; i++)
        #pragma unroll
        for (int j = 0; j < 8; j++)
            #pragma unroll
            for (int l = 0; l < 4; l++) acc[i][j][l] = 0.f;

    const int ntiles = K / BK;

    #define ISSUE_TILE(t, buf) do {                                            \
        __half* As_ = smh + (buf) * STAGE_HALVES;                               \
        __half* Bs_ = As_ + BM * HSTRIDE;                                       \
        int k0_ = (t) * BK;                                                     \
        _Pragma("unroll")                                                       \
        for (int u = 0; u < 4; u++) {                                           \
            int i = tid + u * 256;                                              \
            int r = i >> 3, c = i & 7;                                          \
            cp16(&As_[r * HSTRIDE + c * 8],                                     \
                 &A[(size_t)(bm + r) * K + k0_ + c * 8]);                       \
        }                                                                       \
        _Pragma("unroll")                                                       \
        for (int u = 0; u < 4; u++) {                                           \
            int i = tid + u * 256;                                              \
            int r = i >> 3, c = i & 7;                                          \
            cp16(&Bs_[r * HSTRIDE + c * 8],                                     \
                 &Bt[(size_t)(bn + r) * K + k0_ + c * 8]);                      \
        }                                                                       \
        asm volatile("cp.async.commit_group;");                                 \
    } while (0)

    ISSUE_TILE(0, 0);
    if (ntiles > 1) ISSUE_TILE(1, 1);

    int buf = 0;
    for (int t = 0; t < ntiles; t++) {
        if (t + 1 < ntiles) asm volatile("cp.async.wait_group 1;");
        else                asm volatile("cp.async.wait_group 0;");
        __syncthreads();

        if (t + 2 < ntiles) {
            int nb = buf + 2; if (nb >= NSTAGE) nb -= NSTAGE;
            ISSUE_TILE(t + 2, nb);
        }

        const uint32_t aBase = smBase + buf * STAGE_BYTES;
        const uint32_t bBase = aBase + BM * HSTRIDE * 2;

        #pragma unroll
        for (int ks = 0; ks < 4; ks++) {
            uint32_t af[2][4], bf[8][2];
            #pragma unroll
            for (int mt = 0; mt < 2; mt++) {
                ldsm_x4(af[mt],
                        aBase + ((rowA0 + mt * 16) * HSTRIDE + ks * 16 + koffA) * 2);
            }
            #pragma unroll
            for (int ntp = 0; ntp < 4; ntp++) {
                uint32_t r[4];
                ldsm_x4(r, bBase + ((rowB0 + ntp * 16) * HSTRIDE + ks * 16 + koffB) * 2);
                bf[2 * ntp][0]     = r[0];
                bf[2 * ntp][1]     = r[1];
                bf[2 * ntp + 1][0] = r[2];
                bf[2 * ntp + 1][1] = r[3];
            }
            #pragma unroll
            for (int mt = 0; mt < 2; mt++)
                #pragma unroll
                for (int nt = 0; nt < 8; nt++)
                    mma_f16(acc[mt][nt], af[mt], bf[nt]);
        }

        buf++; if (buf >= NSTAGE) buf = 0;
    }

    if (mode == 3) {
        __half* Ch = (__half*)Cv;
        #pragma unroll
        for (int mt = 0; mt < 2; mt++) {
            #pragma unroll
            for (int ntp = 0; ntp < 4; ntp++) {
                int m0 = bm + wm * 32 + mt * 16 + gid;
                int oc = (bn >> 1) + wn * 32 + ntp * 8 + tg * 2;
                float* g = acc[mt][2 * ntp];
                float* u = acc[mt][2 * ntp + 1];
                *(__half2*)&Ch[(size_t)m0 * DI_ + oc] =
                    __floats2half2_rn(gelu_t(g[0]) * u[0], gelu_t(g[1]) * u[1]);
                *(__half2*)&Ch[(size_t)(m0 + 8) * DI_ + oc] =
                    __floats2half2_rn(gelu_t(g[2]) * u[2], gelu_t(g[3]) * u[3]);
            }
        }
        return;
    }

    #pragma unroll
    for (int mt = 0; mt < 2; mt++) {
        #pragma unroll
        for (int nt = 0; nt < 8; nt++) {
            int m0 = bm + wm * 32 + mt * 16 + gid;
            int n0 = bn + wn * 64 + nt * 8 + tg * 2;
            float2 v0 = make_float2(acc[mt][nt][0], acc[mt][nt][1]);
            float2 v1 = make_float2(acc[mt][nt][2], acc[mt][nt][3]);
            if (mode == 1) {
                float2 r0 = *(const float2*)&Res[(size_t)m0 * N + n0];
                float2 r1 = *(const float2*)&Res[(size_t)(m0 + 8) * N + n0];
                v0.x += r0.x; v0.y += r0.y;
                v1.x += r1.x; v1.y += r1.y;
            }
            float* C = (float*)Cv;
            *(float2*)&C[(size_t)m0 * N + n0] = v0;
            *(float2*)&C[(size_t)(m0 + 8) * N + n0] = v1;
        }
    }
}

// =================== attention with exact window-tile skipping ====
// Warp w handles rows rq..rq+15 (rq = 16w). Valid score cols: [rq, rq+143]
// -> QK tiles nt in [2w, 2w+17] (18 of 24); PV slices ks in [w, w+8] (9 of 12).
// Skipped tiles are fully window-masked: probs exactly 0 (exp underflow).
#define QT 64
#define KT 192
#define KTP 72
#define VTP 200
#define ATTN_SMEM_BYTES ((QT * KTP + KT * KTP + DH_ * VTP) * 2 + KT * 4)

__device__ __forceinline__ void rope_h(const float2* __restrict__ tab, int s, int c,
                                       float4 lo, float4 hi, __half2 olo[2], __half2 ohi[2]) {
    float rlo[4], rhi[4];
    #pragma unroll
    for (int l = 0; l < 4; l++) {
        float2 cs = tab[s * 32 + c * 4 + l];
        float x1 = (&lo.x)[l];
        float x2 = (&hi.x)[l];
        rlo[l] = x1 * cs.x - x2 * cs.y;
        rhi[l] = x2 * cs.x + x1 * cs.y;
    }
    olo[0] = __floats2half2_rn(rlo[0], rlo[1]);
    olo[1] = __floats2half2_rn(rlo[2], rlo[3]);
    ohi[0] = __floats2half2_rn(rhi[0], rhi[1]);
    ohi[1] = __floats2half2_rn(rhi[2], rhi[3]);
}

__global__ __launch_bounds__(128)
void attn_mma_kernel(const float* __restrict__ qkv, const int* __restrict__ pmask,
                     const float2* __restrict__ ropeT, __half* __restrict__ out) {
    extern __shared__ __half smh[];
    __half* Qh = smh;
    __half* Kh = Qh + QT * KTP;
    __half* Vt = Kh + KT * KTP;
    float*  pm = (float*)(Vt + DH_ * VTP);

    const int qt0 = blockIdx.x * QT;
    const int h   = blockIdx.y;
    const int b   = blockIdx.z;
    const int tid = threadIdx.x;
    const int lane = tid & 31;
    const int warp = tid >> 5;
    const int gid  = lane >> 2;
    const int tg   = lane & 3;

    for (int i = tid; i < KT; i += 128) {
        int j = qt0 - WIN + i;
        pm[i] = (j < 0 || j >= S_) ? -1e30f : (pmask[b * S_ + j] ? 0.f : -10000.0f);
    }
    #pragma unroll
    for (int it = 0; it < 4; it++) {
        int i = tid + it * 128;
        int r = i >> 3, c = i & 7;
        int s = qt0 + r;
        size_t base = (size_t)(b * S_ + s) * DQKV + h * DH_;
        float4 lo = *(const float4*)&qkv[base + c * 4];
        float4 hi = *(const float4*)&qkv[base + 32 + c * 4];
        __half2 olo[2], ohi[2];
        rope_h(ropeT, s, c, lo, hi, olo, ohi);
        *(__half2*)&Qh[r * KTP + c * 4]      = olo[0];
        *(__half2*)&Qh[r * KTP + c * 4 + 2]  = olo[1];
        *(__half2*)&Qh[r * KTP + 32 + c * 4]     = ohi[0];
        *(__half2*)&Qh[r * KTP + 32 + c * 4 + 2] = ohi[1];
    }
    #pragma unroll
    for (int it = 0; it < 12; it++) {
        int i = tid + it * 128;
        int r = i >> 3, c = i & 7;
        int j = qt0 - WIN + r;
        __half2 olo[2], ohi[2];
        if (j >= 0 && j < S_) {
            size_t base = (size_t)(b * S_ + j) * DQKV + DM_ + h * DH_;
            float4 lo = *(const float4*)&qkv[base + c * 4];
            float4 hi = *(const float4*)&qkv[base + 32 + c * 4];
            rope_h(ropeT, j, c, lo, hi, olo, ohi);
        } else {
            olo[0] = olo[1] = ohi[0] = ohi[1] = __floats2half2_rn(0.f, 0.f);
        }
        *(__half2*)&Kh[r * KTP + c * 4]      = olo[0];
        *(__half2*)&Kh[r * KTP + c * 4 + 2]  = olo[1];
        *(__half2*)&Kh[r * KTP + 32 + c * 4]     = ohi[0];
        *(__half2*)&Kh[r * KTP + 32 + c * 4 + 2] = ohi[1];
    }
    #pragma unroll
    for (int it = 0; it < 24; it++) {
        int i = tid + it * 128;
        int r = i >> 4, c = i & 15;
        int j = qt0 - WIN + r;
        float4 v = make_float4(0.f, 0.f, 0.f, 0.f);
        if (j >= 0 && j < S_)
            v = *(const float4*)&qkv[(size_t)(b * S_ + j) * DQKV + 2 * DM_ + h * DH_ + c * 4];
        Vt[(c * 4 + 0) * VTP + r] = __float2half_rn(v.x);
        Vt[(c * 4 + 1) * VTP + r] = __float2half_rn(v.y);
        Vt[(c * 4 + 2) * VTP + r] = __float2half_rn(v.z);
        Vt[(c * 4 + 3) * VTP + r] = __float2half_rn(v.w);
    }
    __syncthreads();

    const int rq = warp * 16;
    const int ntBase = 2 * warp;      // first live QK tile
    float acc[18][4];
    #pragma unroll
    for (int nt = 0; nt < 18; nt++)
        #pragma unroll
        for (int e = 0; e < 4; e++) acc[nt][e] = 0.f;

    // ---- QK^T over live tiles ----
    #pragma unroll
    for (int ks = 0; ks < 4; ks++) {
        const int kb = ks * 16 + 2 * tg;
        uint32_t a[4];
        a[0] = *(const uint32_t*)&Qh[(rq + gid) * KTP + kb];
        a[1] = *(const uint32_t*)&Qh[(rq + gid + 8) * KTP + kb];
        a[2] = *(const uint32_t*)&Qh[(rq + gid) * KTP + kb + 8];
        a[3] = *(const uint32_t*)&Qh[(rq + gid + 8) * KTP + kb + 8];
        #pragma unroll
        for (int nti = 0; nti < 18; nti++) {
            int n = (ntBase + nti) * 8 + gid;
            uint32_t bfr[2];
            bfr[0] = *(const uint32_t*)&Kh[n * KTP + kb];
            bfr[1] = *(const uint32_t*)&Kh[n * KTP + kb + 8];
            mma_f16(acc[nti], a, bfr);
        }
    }

    // ---- mask + softmax over live tiles ----
    const int ql0 = rq + gid;
    float m0 = -1e30f, m1 = -1e30f;
    #pragma unroll
    for (int nti = 0; nti < 18; nti++) {
        #pragma unroll
        for (int e = 0; e < 4; e++) {
            int col = (ntBase + nti) * 8 + 2 * tg + (e & 1);
            int ql  = ql0 + ((e >> 1) << 3);
            float s = acc[nti][e] * 0.125f + pm[col];
            int d = col - ql - WIN;
            if (d > WIN || d < -WIN) s -= 10000.0f;
            acc[nti][e] = s;
            if (e < 2) m0 = fmaxf(m0, s); else m1 = fmaxf(m1, s);
        }
    }
    m0 = fmaxf(m0, __shfl_xor_sync(0xffffffffu, m0, 1));
    m0 = fmaxf(m0, __shfl_xor_sync(0xffffffffu, m0, 2));
    m1 = fmaxf(m1, __shfl_xor_sync(0xffffffffu, m1, 1));
    m1 = fmaxf(m1, __shfl_xor_sync(0xffffffffu, m1, 2));

    float s0 = 0.f, s1 = 0.f;
    #pragma unroll
    for (int nti = 0; nti < 18; nti++) {
        float e0 = expf(acc[nti][0] - m0);
        float e1 = expf(acc[nti][1] - m0);
        float e2 = expf(acc[nti][2] - m1);
        float e3 = expf(acc[nti][3] - m1);
        acc[nti][0] = e0; acc[nti][1] = e1; acc[nti][2] = e2; acc[nti][3] = e3;
        s0 += e0 + e1; s1 += e2 + e3;
    }
    s0 += __shfl_xor_sync(0xffffffffu, s0, 1);
    s0 += __shfl_xor_sync(0xffffffffu, s0, 2);
    s1 += __shfl_xor_sync(0xffffffffu, s1, 1);
    s1 += __shfl_xor_sync(0xffffffffu, s1, 2);
    const float inv0 = 1.0f / s0;
    const float inv1 = 1.0f / s1;

    // ---- PV over live k-slices: absolute slice = warp + ksl, ksl in [0,9) ----
    float accV[8][4];
    #pragma unroll
    for (int nt = 0; nt < 8; nt++)
        #pragma unroll
        for (int e = 0; e < 4; e++) accV[nt][e] = 0.f;

    #pragma unroll
    for (int ksl = 0; ksl < 9; ksl++) {
        uint32_t a[4];
        __half2 h0 = __floats2half2_rn(acc[2 * ksl][0] * inv0,     acc[2 * ksl][1] * inv0);
        __half2 h1 = __floats2half2_rn(acc[2 * ksl][2] * inv1,     acc[2 * ksl][3] * inv1);
        __half2 h2 = __floats2half2_rn(acc[2 * ksl + 1][0] * inv0, acc[2 * ksl + 1][1] * inv0);
        __half2 h3 = __floats2half2_rn(acc[2 * ksl + 1][2] * inv1, acc[2 * ksl + 1][3] * inv1);
        a[0] = *(uint32_t*)&h0;
        a[1] = *(uint32_t*)&h1;
        a[2] = *(uint32_t*)&h2;
        a[3] = *(uint32_t*)&h3;
        const int kb = (warp + ksl) * 16 + 2 * tg;
        #pragma unroll
        for (int nt = 0; nt < 8; nt++) {
            int n = nt * 8 + gid;
            uint32_t bfr[2];
            bfr[0] = *(const uint32_t*)&Vt[n * VTP + kb];
            bfr[1] = *(const uint32_t*)&Vt[n * VTP + kb + 8];
            mma_f16(accV[nt], a, bfr);
        }
    }

    #pragma unroll
    for (int nt = 0; nt < 8; nt++) {
        int col = h * DH_ + nt * 8 + 2 * tg;
        size_t r0 = (size_t)(b * S_ + qt0 + ql0) * DM_ + col;
        size_t r1 = (size_t)(b * S_ + qt0 + ql0 + 8) * DM_ + col;
        *(__half2*)&out[r0] = __floats2half2_rn(accV[nt][0], accV[nt][1]);
        *(__half2*)&out[r1] = __floats2half2_rn(accV[nt][2], accV[nt][3]);
    }
}

// ---------------- launch ----------------
extern "C" void kernel_launch(void* const* d_in, const int* in_sizes, int n_in,
                              void* d_out, int out_size) {
    const float* x          = (const float*)d_in[0];
    const int*   pmask      = (const int*)  d_in[1];
    const float* w_qkv      = (const float*)d_in[2];
    const float* w_o        = (const float*)d_in[3];
    const float* gamma_attn = (const float*)d_in[4];
    const float* gamma_mlp  = (const float*)d_in[5];
    const float* w_i0       = (const float*)d_in[6];
    const float* w_i1       = (const float*)d_in[7];
    const float* w_mo       = (const float*)d_in[8];
    float* out = (float*)d_out;

    __half *h, *attn, *act, *wqkv, *wo, *wi01, *wmo;
    float *qkv, *x1;
    float2* ropeT;
    cudaGetSymbolAddress((void**)&h,    g_h);
    cudaGetSymbolAddress((void**)&qkv,  g_qkv);
    cudaGetSymbolAddress((void**)&attn, g_attn);
    cudaGetSymbolAddress((void**)&x1,   g_x1);
    cudaGetSymbolAddress((void**)&act,  g_act);
    cudaGetSymbolAddress((void**)&ropeT, g_rope);
    cudaGetSymbolAddress((void**)&wqkv, g_wqkv);
    cudaGetSymbolAddress((void**)&wo,   g_wo);
    cudaGetSymbolAddress((void**)&wi01, g_wi01);
    cudaGetSymbolAddress((void**)&wmo,  g_wmo);

    cudaFuncSetAttribute(mma_gemm_kernel,
                         cudaFuncAttributeMaxDynamicSharedMemorySize, GEMM_SMEM_BYTES);
    cudaFuncSetAttribute(attn_mma_kernel,
                         cudaFuncAttributeMaxDynamicSharedMemorySize, ATTN_SMEM_BYTES);

    wprep_kernel<<<dim3(DI_ / 32, DQKV / 32, 6), dim3(32, 8)>>>(
        w_qkv, w_o, w_i0, w_i1, w_mo, wqkv, wo, wi01, wmo, ropeT);

    rmsnorm_kernel<<<ROWS, 256>>>(x, gamma_attn, h);
    mma_gemm_kernel<<<dim3(DQKV / BN, ROWS / BM), 256, GEMM_SMEM_BYTES>>>(
        h, wqkv, nullptr, qkv, ROWS, DQKV, DM_, 0);
    attn_mma_kernel<<<dim3(S_ / QT, H_, B_), 128, ATTN_SMEM_BYTES>>>(qkv, pmask, ropeT, attn);
    mma_gemm_kernel<<<dim3(DM_ / BN, ROWS / BM), 256, GEMM_SMEM_BYTES>>>(
        attn, wo, x, x1, ROWS, DM_, DM_, 1);
    rmsnorm_kernel<<<ROWS, 256>>>(x1, gamma_mlp, h);
    mma_gemm_kernel<<<dim3(2 * DI_ / BN, ROWS / BM), 256, GEMM_SMEM_BYTES>>>(
        h, wi01, nullptr, act, ROWS, 2 * DI_, DM_, 3);
    mma_gemm_kernel<<<dim3(DM_ / BN, ROWS / BM), 256, GEMM_SMEM_BYTES>>>(
        act, wmo, x1, out, ROWS, DM_, DI_, 1);
}

// round 17
// speedup vs baseline: 1.0721x; 1.0376x over previous
#include <cuda_runtime.h>
#include <cuda_fp16.h>
#include <math.h>
#include <stdint.h>

// ---------------- problem constants ----------------
#define B_   2
#define S_   4096
#define DM_  768
#define DI_  1152
#define H_   12
#define DH_  64
#define ROWS (B_ * S_)          // 8192
#define DQKV (3 * DM_)          // 2304
#define WIN  64                 // WINDOW/2

// ---------------- scratch ----------------
__device__ __half g_h[ROWS * DM_];
__device__ __half g_qkvh[ROWS * DQKV];   // fp16, rope pre-applied to q,k
__device__ __half g_attn[ROWS * DM_];
__device__ float  g_x1[ROWS * DM_];
__device__ __half g_act[ROWS * DI_];
__device__ float2 g_rope[S_ * 32];
__device__ __half g_wqkv[DQKV * DM_];
__device__ __half g_wo  [DM_ * DM_];
__device__ __half g_wi01[2 * DI_ * DM_];
__device__ __half g_wmo [DM_ * DI_];

__device__ __forceinline__ float warpSum(float v) {
    #pragma unroll
    for (int o = 16; o; o >>= 1) v += __shfl_xor_sync(0xffffffffu, v, o);
    return v;
}

// ---------------- merged prep: 5 weights + rope table ----------------
__global__ void wprep_kernel(const float* __restrict__ w_qkv, const float* __restrict__ w_o,
                             const float* __restrict__ w_i0,  const float* __restrict__ w_i1,
                             const float* __restrict__ w_mo,
                             __half* __restrict__ o_qkv, __half* __restrict__ o_o,
                             __half* __restrict__ o_i01, __half* __restrict__ o_mo,
                             float2* __restrict__ ropeTab) {
    int tx = threadIdx.x, ty = threadIdx.y;
    if (blockIdx.z == 5) {
        int bid = blockIdx.y * gridDim.x + blockIdx.x;
        int idx = bid * 256 + ty * 32 + tx;
        if (idx < S_ * 32) {
            int s = idx >> 5, d = idx & 31;
            float w = (float)(2 * d) / (float)DH_;
            float inv_freq = 1.0f / powf(10000.0f, w);
            float ang = (float)s * inv_freq;
            ropeTab[idx] = make_float2(cosf(ang), sinf(ang));
        }
        return;
    }
    const float* in; __half* out; int K, N, mapMode;
    switch (blockIdx.z) {
        case 0: in = w_qkv; out = o_qkv; K = DM_; N = DQKV; mapMode = 0; break;
        case 1: in = w_o;   out = o_o;   K = DM_; N = DM_;  mapMode = 0; break;
        case 2: in = w_i0;  out = o_i01; K = DM_; N = DI_;  mapMode = 1; break;
        case 3: in = w_i1;  out = o_i01; K = DM_; N = DI_;  mapMode = 2; break;
        default:in = w_mo;  out = o_mo;  K = DI_; N = DM_;  mapMode = 0; break;
    }
    int k0 = blockIdx.x * 32, n0 = blockIdx.y * 32;
    if (k0 >= K || n0 >= N) return;
    __shared__ float t[32][33];
    #pragma unroll
    for (int i = ty; i < 32; i += 8)
        t[i][tx] = in[(size_t)(k0 + i) * N + n0 + tx];
    __syncthreads();
    #pragma unroll
    for (int i = ty; i < 32; i += 8) {
        int n = n0 + i;
        int row;
        if (mapMode == 0)      row = n;
        else if (mapMode == 1) row = ((n >> 3) << 4) + (n & 7);
        else                   row = ((n >> 3) << 4) + 8 + (n & 7);
        out[(size_t)row * K + k0 + tx] = __float2half_rn(t[tx][i]);
    }
}

// ---------------- RMSNorm ----------------
__global__ void rmsnorm_kernel(const float* __restrict__ x,
                               const float* __restrict__ gamma,
                               __half* __restrict__ o) {
    int row = blockIdx.x;
    const float4* xr = (const float4*)(x + (size_t)row * DM_);
    const int tid = threadIdx.x;
    float4 v4 = make_float4(0.f, 0.f, 0.f, 0.f);
    if (tid < 192) v4 = xr[tid];
    float s = v4.x * v4.x + v4.y * v4.y + v4.z * v4.z + v4.w * v4.w;
    __shared__ float red[8];
    float w = warpSum(s);
    if ((tid & 31) == 0) red[tid >> 5] = w;
    __syncthreads();
    float tot = 0.f;
    #pragma unroll
    for (int i = 0; i < 8; i++) tot += red[i];
    float inv = rsqrtf(tot / (float)DM_ + 1e-5f);
    if (tid < 192) {
        float4 g4 = ((const float4*)gamma)[tid];
        __half2 h0 = __floats2half2_rn(v4.x * inv * g4.x, v4.y * inv * g4.y);
        __half2 h1 = __floats2half2_rn(v4.z * inv * g4.z, v4.w * inv * g4.w);
        __half* orow = o + (size_t)row * DM_;
        *(__half2*)&orow[tid * 4]     = h0;
        *(__half2*)&orow[tid * 4 + 2] = h1;
    }
}

// =================== fp16 tensor-core GEMM (128x128x64, 3-stage, ldmatrix) ===
// mode 0: C=acc(f32) ; 1: C=Res+acc(f32) ; 3: fused gate/up (fp16)
// mode 4: qkv epilogue -> fp16, rope applied to q,k columns
#define BM 128
#define BN 128
#define BK 64
#define HSTRIDE 72
#define STAGE_HALVES ((BM + BN) * HSTRIDE)
#define STAGE_BYTES (STAGE_HALVES * 2)
#define NSTAGE 3
#define GEMM_SMEM_BYTES (NSTAGE * STAGE_BYTES)

__device__ __forceinline__ void mma_f16(float c[4], const uint32_t a[4], const uint32_t b[2]) {
    asm volatile(
        "mma.sync.aligned.m16n8k16.row.col.f32.f16.f16.f32 "
        "{%0,%1,%2,%3}, {%4,%5,%6,%7}, {%8,%9}, {%0,%1,%2,%3};"
        : "+f"(c[0]), "+f"(c[1]), "+f"(c[2]), "+f"(c[3])
        : "r"(a[0]), "r"(a[1]), "r"(a[2]), "r"(a[3]), "r"(b[0]), "r"(b[1]));
}

__device__ __forceinline__ void ldsm_x4(uint32_t r[4], uint32_t saddr) {
    asm volatile("ldmatrix.sync.aligned.m8n8.x4.shared.b16 {%0,%1,%2,%3}, [%4];"
        : "=r"(r[0]), "=r"(r[1]), "=r"(r[2]), "=r"(r[3]) : "r"(saddr));
}

__device__ __forceinline__ void cp16(const __half* dst_smem, const __half* src) {
    uint32_t d = (uint32_t)__cvta_generic_to_shared(dst_smem);
    asm volatile("cp.async.cg.shared.global [%0], [%1], 16;" :: "r"(d), "l"(src));
}

__device__ __forceinline__ void cp16z(const __half* dst_smem, const __half* src, int szbytes) {
    uint32_t d = (uint32_t)__cvta_generic_to_shared(dst_smem);
    asm volatile("cp.async.cg.shared.global [%0], [%1], 16, %2;"
        :: "r"(d), "l"(src), "r"(szbytes));
}

__device__ __forceinline__ float gelu_t(float x) {
    float t = tanhf(0.7978845608028654f * (x + 0.044715f * x * x * x));
    return 0.5f * x * (1.0f + t);
}

__global__ __launch_bounds__(256, 2)
void mma_gemm_kernel(const __half* __restrict__ A, const __half* __restrict__ Bt,
                     const float* __restrict__ Res, void* __restrict__ Cv,
                     const float2* __restrict__ ropeT,
                     int M, int N, int K, int mode) {
    extern __shared__ __half smh[];

    const int tid  = threadIdx.x;
    const int lane = tid & 31;
    const int warp = tid >> 5;
    const int gid  = lane >> 2;
    const int tg   = lane & 3;
    const int wm   = warp >> 1;
    const int wn   = warp & 1;

    const int bm = blockIdx.y * BM;
    const int bn = blockIdx.x * BN;

    const uint32_t smBase = (uint32_t)__cvta_generic_to_shared(smh);
    const int rowA0 = wm * 32 + (lane & 15);
    const int koffA = (lane >> 4) << 3;
    const int rowB0 = wn * 64 + (lane & 7) + ((lane >> 4) << 3);
    const int koffB = ((lane >> 3) & 1) << 3;

    float acc[2][8][4];
    #pragma unroll
    for (int i = 0; i < 2; i++)
        #pragma unroll
        for (int j = 0; j < 8; j++)
            #pragma unroll
            for (int l = 0; l < 4; l++) acc[i][j][l] = 0.f;

    const int ntiles = K / BK;

    #define ISSUE_TILE(t, buf) do {                                            \
        __half* As_ = smh + (buf) * STAGE_HALVES;                               \
        __half* Bs_ = As_ + BM * HSTRIDE;                                       \
        int k0_ = (t) * BK;                                                     \
        _Pragma("unroll")                                                       \
        for (int u = 0; u < 4; u++) {                                           \
            int i = tid + u * 256;                                              \
            int r = i >> 3, c = i & 7;                                          \
            cp16(&As_[r * HSTRIDE + c * 8],                                     \
                 &A[(size_t)(bm + r) * K + k0_ + c * 8]);                       \
        }                                                                       \
        _Pragma("unroll")                                                       \
        for (int u = 0; u < 4; u++) {                                           \
            int i = tid + u * 256;                                              \
            int r = i >> 3, c = i & 7;                                          \
            cp16(&Bs_[r * HSTRIDE + c * 8],                                     \
                 &Bt[(size_t)(bn + r) * K + k0_ + c * 8]);                      \
        }                                                                       \
        asm volatile("cp.async.commit_group;");                                 \
    } while (0)

    ISSUE_TILE(0, 0);
    if (ntiles > 1) ISSUE_TILE(1, 1);

    int buf = 0;
    for (int t = 0; t < ntiles; t++) {
        if (t + 1 < ntiles) asm volatile("cp.async.wait_group 1;");
        else                asm volatile("cp.async.wait_group 0;");
        __syncthreads();

        if (t + 2 < ntiles) {
            int nb = buf + 2; if (nb >= NSTAGE) nb -= NSTAGE;
            ISSUE_TILE(t + 2, nb);
        }

        const uint32_t aBase = smBase + buf * STAGE_BYTES;
        const uint32_t bBase = aBase + BM * HSTRIDE * 2;

        #pragma unroll
        for (int ks = 0; ks < 4; ks++) {
            uint32_t af[2][4], bf[8][2];
            #pragma unroll
            for (int mt = 0; mt < 2; mt++) {
                ldsm_x4(af[mt],
                        aBase + ((rowA0 + mt * 16) * HSTRIDE + ks * 16 + koffA) * 2);
            }
            #pragma unroll
            for (int ntp = 0; ntp < 4; ntp++) {
                uint32_t r[4];
                ldsm_x4(r, bBase + ((rowB0 + ntp * 16) * HSTRIDE + ks * 16 + koffB) * 2);
                bf[2 * ntp][0]     = r[0];
                bf[2 * ntp][1]     = r[1];
                bf[2 * ntp + 1][0] = r[2];
                bf[2 * ntp + 1][1] = r[3];
            }
            #pragma unroll
            for (int mt = 0; mt < 2; mt++)
                #pragma unroll
                for (int nt = 0; nt < 8; nt++)
                    mma_f16(acc[mt][nt], af[mt], bf[nt]);
        }

        buf++; if (buf >= NSTAGE) buf = 0;
    }

    if (mode == 4) {
        // qkv epilogue: rope q,k pairs (d, d+32) = (acc[mt][ntp], acc[mt][ntp+4]),
        // v columns plain. All fp32 math then one fp16 rounding (== R16 path).
        __half* Ch = (__half*)Cv;
        #pragma unroll
        for (int mt = 0; mt < 2; mt++) {
            int m0 = bm + wm * 32 + mt * 16 + gid;
            #pragma unroll
            for (int ntp = 0; ntp < 4; ntp++) {
                int n0 = bn + wn * 64 + ntp * 8 + tg * 2;
                float* lo = acc[mt][ntp];
                float* hi = acc[mt][ntp + 4];
                if (n0 < 2 * DM_) {
                    int d0 = n0 & 63;               // < 32
                    int s0 = m0 & (S_ - 1);
                    int s1 = (m0 + 8) & (S_ - 1);
                    float2 c00 = ropeT[s0 * 32 + d0];
                    float2 c01 = ropeT[s0 * 32 + d0 + 1];
                    float2 c10 = ropeT[s1 * 32 + d0];
                    float2 c11 = ropeT[s1 * 32 + d0 + 1];
                    float l0 = lo[0] * c00.x - hi[0] * c00.y;
                    float h0 = hi[0] * c00.x + lo[0] * c00.y;
                    float l1 = lo[1] * c01.x - hi[1] * c01.y;
                    float h1 = hi[1] * c01.x + lo[1] * c01.y;
                    float l2 = lo[2] * c10.x - hi[2] * c10.y;
                    float h2 = hi[2] * c10.x + lo[2] * c10.y;
                    float l3 = lo[3] * c11.x - hi[3] * c11.y;
                    float h3 = hi[3] * c11.x + lo[3] * c11.y;
                    *(__half2*)&Ch[(size_t)m0 * N + n0]            = __floats2half2_rn(l0, l1);
                    *(__half2*)&Ch[(size_t)m0 * N + n0 + 32]       = __floats2half2_rn(h0, h1);
                    *(__half2*)&Ch[(size_t)(m0 + 8) * N + n0]      = __floats2half2_rn(l2, l3);
                    *(__half2*)&Ch[(size_t)(m0 + 8) * N + n0 + 32] = __floats2half2_rn(h2, h3);
                } else {
                    *(__half2*)&Ch[(size_t)m0 * N + n0]            = __floats2half2_rn(lo[0], lo[1]);
                    *(__half2*)&Ch[(size_t)(m0 + 8) * N + n0]      = __floats2half2_rn(lo[2], lo[3]);
                    *(__half2*)&Ch[(size_t)m0 * N + n0 + 32]       = __floats2half2_rn(hi[0], hi[1]);
                    *(__half2*)&Ch[(size_t)(m0 + 8) * N + n0 + 32] = __floats2half2_rn(hi[2], hi[3]);
                }
            }
        }
        return;
    }

    if (mode == 3) {
        __half* Ch = (__half*)Cv;
        #pragma unroll
        for (int mt = 0; mt < 2; mt++) {
            #pragma unroll
            for (int ntp = 0; ntp < 4; ntp++) {
                int m0 = bm + wm * 32 + mt * 16 + gid;
                int oc = (bn >> 1) + wn * 32 + ntp * 8 + tg * 2;
                float* g = acc[mt][2 * ntp];
                float* u = acc[mt][2 * ntp + 1];
                *(__half2*)&Ch[(size_t)m0 * DI_ + oc] =
                    __floats2half2_rn(gelu_t(g[0]) * u[0], gelu_t(g[1]) * u[1]);
                *(__half2*)&Ch[(size_t)(m0 + 8) * DI_ + oc] =
                    __floats2half2_rn(gelu_t(g[2]) * u[2], gelu_t(g[3]) * u[3]);
            }
        }
        return;
    }

    #pragma unroll
    for (int mt = 0; mt < 2; mt++) {
        #pragma unroll
        for (int nt = 0; nt < 8; nt++) {
            int m0 = bm + wm * 32 + mt * 16 + gid;
            int n0 = bn + wn * 64 + nt * 8 + tg * 2;
            float2 v0 = make_float2(acc[mt][nt][0], acc[mt][nt][1]);
            float2 v1 = make_float2(acc[mt][nt][2], acc[mt][nt][3]);
            if (mode == 1) {
                float2 r0 = *(const float2*)&Res[(size_t)m0 * N + n0];
                float2 r1 = *(const float2*)&Res[(size_t)(m0 + 8) * N + n0];
                v0.x += r0.x; v0.y += r0.y;
                v1.x += r1.x; v1.y += r1.y;
            }
            float* C = (float*)Cv;
            *(float2*)&C[(size_t)m0 * N + n0] = v0;
            *(float2*)&C[(size_t)(m0 + 8) * N + n0] = v1;
        }
    }
}

// =================== attention: cp.async loader, window-tile skipping ====
#define QT 64
#define KT 192
#define KTP 72
#define VTP 200
#define ATTN_SMEM_BYTES ((QT * KTP + KT * KTP + DH_ * VTP) * 2 + KT * 4)

__global__ __launch_bounds__(128)
void attn_mma_kernel(const __half* __restrict__ qkvh, const int* __restrict__ pmask,
                     __half* __restrict__ out) {
    extern __shared__ __half smh[];
    __half* Qh = smh;
    __half* Kh = Qh + QT * KTP;
    __half* Vt = Kh + KT * KTP;
    float*  pm = (float*)(Vt + DH_ * VTP);

    const int qt0 = blockIdx.x * QT;
    const int h   = blockIdx.y;
    const int b   = blockIdx.z;
    const int tid = threadIdx.x;
    const int lane = tid & 31;
    const int warp = tid >> 5;
    const int gid  = lane >> 2;
    const int tg   = lane & 3;

    // Q: 64 rows x 8 16B-chunks, pure copy (rope already applied)
    #pragma unroll
    for (int it = 0; it < 4; it++) {
        int i = tid + it * 128;
        int r = i >> 3, c = i & 7;
        cp16(&Qh[r * KTP + c * 8],
             &qkvh[(size_t)(b * S_ + qt0 + r) * DQKV + h * DH_ + c * 8]);
    }
    // K: 192 rows, zero-fill out-of-range
    #pragma unroll
    for (int it = 0; it < 12; it++) {
        int i = tid + it * 128;
        int r = i >> 3, c = i & 7;
        int j = qt0 - WIN + r;
        int ok = (j >= 0 && j < S_);
        int jc = ok ? j : 0;
        cp16z(&Kh[r * KTP + c * 8],
              &qkvh[(size_t)(b * S_ + jc) * DQKV + DM_ + h * DH_ + c * 8],
              ok ? 16 : 0);
    }
    asm volatile("cp.async.commit_group;");

    for (int i = tid; i < KT; i += 128) {
        int j = qt0 - WIN + i;
        pm[i] = (j < 0 || j >= S_) ? -1e30f : (pmask[b * S_ + j] ? 0.f : -10000.0f);
    }
    // V transpose: fp16 half2 loads, scalar stores
    #pragma unroll
    for (int it = 0; it < 48; it++) {
        int i = tid + it * 128;
        int r = i >> 5, c2 = i & 31;
        int j = qt0 - WIN + r;
        __half2 v = __floats2half2_rn(0.f, 0.f);
        if (j >= 0 && j < S_)
            v = *(const __half2*)&qkvh[(size_t)(b * S_ + j) * DQKV + 2 * DM_ + h * DH_ + c2 * 2];
        Vt[(c2 * 2) * VTP + r]     = __low2half(v);
        Vt[(c2 * 2 + 1) * VTP + r] = __high2half(v);
    }
    asm volatile("cp.async.wait_group 0;");
    __syncthreads();

    const int rq = warp * 16;
    const int ntBase = 2 * warp;
    float acc[18][4];
    #pragma unroll
    for (int nt = 0; nt < 18; nt++)
        #pragma unroll
        for (int e = 0; e < 4; e++) acc[nt][e] = 0.f;

    #pragma unroll
    for (int ks = 0; ks < 4; ks++) {
        const int kb = ks * 16 + 2 * tg;
        uint32_t a[4];
        a[0] = *(const uint32_t*)&Qh[(rq + gid) * KTP + kb];
        a[1] = *(const uint32_t*)&Qh[(rq + gid + 8) * KTP + kb];
        a[2] = *(const uint32_t*)&Qh[(rq + gid) * KTP + kb + 8];
        a[3] = *(const uint32_t*)&Qh[(rq + gid + 8) * KTP + kb + 8];
        #pragma unroll
        for (int nti = 0; nti < 18; nti++) {
            int n = (ntBase + nti) * 8 + gid;
            uint32_t bfr[2];
            bfr[0] = *(const uint32_t*)&Kh[n * KTP + kb];
            bfr[1] = *(const uint32_t*)&Kh[n * KTP + kb + 8];
            mma_f16(acc[nti], a, bfr);
        }
    }

    const int ql0 = rq + gid;
    float m0 = -1e30f, m1 = -1e30f;
    #pragma unroll
    for (int nti = 0; nti < 18; nti++) {
        #pragma unroll
        for (int e = 0; e < 4; e++) {
            int col = (ntBase + nti) * 8 + 2 * tg + (e & 1);
            int ql  = ql0 + ((e >> 1) << 3);
            float s = acc[nti][e] * 0.125f + pm[col];
            int d = col - ql - WIN;
            if (d > WIN || d < -WIN) s -= 10000.0f;
            acc[nti][e] = s;
            if (e < 2) m0 = fmaxf(m0, s); else m1 = fmaxf(m1, s);
        }
    }
    m0 = fmaxf(m0, __shfl_xor_sync(0xffffffffu, m0, 1));
    m0 = fmaxf(m0, __shfl_xor_sync(0xffffffffu, m0, 2));
    m1 = fmaxf(m1, __shfl_xor_sync(0xffffffffu, m1, 1));
    m1 = fmaxf(m1, __shfl_xor_sync(0xffffffffu, m1, 2));

    float s0 = 0.f, s1 = 0.f;
    #pragma unroll
    for (int nti = 0; nti < 18; nti++) {
        float e0 = expf(acc[nti][0] - m0);
        float e1 = expf(acc[nti][1] - m0);
        float e2 = expf(acc[nti][2] - m1);
        float e3 = expf(acc[nti][3] - m1);
        acc[nti][0] = e0; acc[nti][1] = e1; acc[nti][2] = e2; acc[nti][3] = e3;
        s0 += e0 + e1; s1 += e2 + e3;
    }
    s0 += __shfl_xor_sync(0xffffffffu, s0, 1);
    s0 += __shfl_xor_sync(0xffffffffu, s0, 2);
    s1 += __shfl_xor_sync(0xffffffffu, s1, 1);
    s1 += __shfl_xor_sync(0xffffffffu, s1, 2);
    const float inv0 = 1.0f / s0;
    const float inv1 = 1.0f / s1;

    float accV[8][4];
    #pragma unroll
    for (int nt = 0; nt < 8; nt++)
        #pragma unroll
        for (int e = 0; e < 4; e++) accV[nt][e] = 0.f;

    #pragma unroll
    for (int ksl = 0; ksl < 9; ksl++) {
        uint32_t a[4];
        __half2 h0 = __floats2half2_rn(acc[2 * ksl][0] * inv0,     acc[2 * ksl][1] * inv0);
        __half2 h1 = __floats2half2_rn(acc[2 * ksl][2] * inv1,     acc[2 * ksl][3] * inv1);
        __half2 h2 = __floats2half2_rn(acc[2 * ksl + 1][0] * inv0, acc[2 * ksl + 1][1] * inv0);
        __half2 h3 = __floats2half2_rn(acc[2 * ksl + 1][2] * inv1, acc[2 * ksl + 1][3] * inv1);
        a[0] = *(uint32_t*)&h0;
        a[1] = *(uint32_t*)&h1;
        a[2] = *(uint32_t*)&h2;
        a[3] = *(uint32_t*)&h3;
        const int kb = (warp + ksl) * 16 + 2 * tg;
        #pragma unroll
        for (int nt = 0; nt < 8; nt++) {
            int n = nt * 8 + gid;
            uint32_t bfr[2];
            bfr[0] = *(const uint32_t*)&Vt[n * VTP + kb];
            bfr[1] = *(const uint32_t*)&Vt[n * VTP + kb + 8];
            mma_f16(accV[nt], a, bfr);
        }
    }

    #pragma unroll
    for (int nt = 0; nt < 8; nt++) {
        int col = h * DH_ + nt * 8 + 2 * tg;
        size_t r0 = (size_t)(b * S_ + qt0 + ql0) * DM_ + col;
        size_t r1 = (size_t)(b * S_ + qt0 + ql0 + 8) * DM_ + col;
        *(__half2*)&out[r0] = __floats2half2_rn(accV[nt][0], accV[nt][1]);
        *(__half2*)&out[r1] = __floats2half2_rn(accV[nt][2], accV[nt][3]);
    }
}

// ---------------- launch ----------------
extern "C" void kernel_launch(void* const* d_in, const int* in_sizes, int n_in,
                              void* d_out, int out_size) {
    const float* x          = (const float*)d_in[0];
    const int*   pmask      = (const int*)  d_in[1];
    const float* w_qkv      = (const float*)d_in[2];
    const float* w_o        = (const float*)d_in[3];
    const float* gamma_attn = (const float*)d_in[4];
    const float* gamma_mlp  = (const float*)d_in[5];
    const float* w_i0       = (const float*)d_in[6];
    const float* w_i1       = (const float*)d_in[7];
    const float* w_mo       = (const float*)d_in[8];
    float* out = (float*)d_out;

    __half *h, *qkvh, *attn, *act, *wqkv, *wo, *wi01, *wmo;
    float *x1;
    float2* ropeT;
    cudaGetSymbolAddress((void**)&h,    g_h);
    cudaGetSymbolAddress((void**)&qkvh, g_qkvh);
    cudaGetSymbolAddress((void**)&attn, g_attn);
    cudaGetSymbolAddress((void**)&x1,   g_x1);
    cudaGetSymbolAddress((void**)&act,  g_act);
    cudaGetSymbolAddress((void**)&ropeT, g_rope);
    cudaGetSymbolAddress((void**)&wqkv, g_wqkv);
    cudaGetSymbolAddress((void**)&wo,   g_wo);
    cudaGetSymbolAddress((void**)&wi01, g_wi01);
    cudaGetSymbolAddress((void**)&wmo,  g_wmo);

    cudaFuncSetAttribute(mma_gemm_kernel,
                         cudaFuncAttributeMaxDynamicSharedMemorySize, GEMM_SMEM_BYTES);
    cudaFuncSetAttribute(attn_mma_kernel,
                         cudaFuncAttributeMaxDynamicSharedMemorySize, ATTN_SMEM_BYTES);

    wprep_kernel<<<dim3(DI_ / 32, DQKV / 32, 6), dim3(32, 8)>>>(
        w_qkv, w_o, w_i0, w_i1, w_mo, wqkv, wo, wi01, wmo, ropeT);

    rmsnorm_kernel<<<ROWS, 256>>>(x, gamma_attn, h);
    // QKV projection with fused rope + fp16 epilogue
    mma_gemm_kernel<<<dim3(DQKV / BN, ROWS / BM), 256, GEMM_SMEM_BYTES>>>(
        h, wqkv, nullptr, qkvh, ropeT, ROWS, DQKV, DM_, 4);
    attn_mma_kernel<<<dim3(S_ / QT, H_, B_), 128, ATTN_SMEM_BYTES>>>(qkvh, pmask, attn);
    mma_gemm_kernel<<<dim3(DM_ / BN, ROWS / BM), 256, GEMM_SMEM_BYTES>>>(
        attn, wo, x, x1, nullptr, ROWS, DM_, DM_, 1);
    rmsnorm_kernel<<<ROWS, 256>>>(x1, gamma_mlp, h);
    mma_gemm_kernel<<<dim3(2 * DI_ / BN, ROWS / BM), 256, GEMM_SMEM_BYTES>>>(
        h, wi01, nullptr, act, nullptr, ROWS, 2 * DI_, DM_, 3);
    mma_gemm_kernel<<<dim3(DM_ / BN, ROWS / BM), 256, GEMM_SMEM_BYTES>>>(
        act, wmo, x1, out, nullptr, ROWS, DM_, DI_, 1);
}